// round 9
// baseline (speedup 1.0000x reference)
#include <cuda_runtime.h>
#include <math.h>

#define B_ 8
#define T_ 2048
#define C_ 1024
#define H_ 64

// Scratch for projections (device globals: allocation-free)
__device__ float g_q[B_ * T_ * H_];
__device__ float g_k[B_ * T_ * H_];
__device__ float g_v[B_ * T_ * H_];

// ---------------------------------------------------------------------------
// Projection GEMM: out[m][h] = sum_c x[m][c] * W[h][c]
// M = B*T = 16384, N = 64, K = 1024.  blockIdx.y selects {k,q,v}.
// BM=128, BN=64, BK=32; 256 threads; 8x4 micro-tile per thread.
// ---------------------------------------------------------------------------
#define PM 128
#define PKC 32
#define PSTR 36  // smem row stride (floats), float4-aligned, odd multiple of 4

__global__ __launch_bounds__(256, 1)
void proj_kernel(const float* __restrict__ x,
                 const float* __restrict__ Wk,
                 const float* __restrict__ Wq,
                 const float* __restrict__ Wv)
{
    __shared__ float xs[PM][PSTR];
    __shared__ float ws[H_][PSTR];

    const float* W;
    float* out;
    if (blockIdx.y == 0)      { W = Wk; out = g_k; }
    else if (blockIdx.y == 1) { W = Wq; out = g_q; }
    else                      { W = Wv; out = g_v; }

    const int tid = threadIdx.x;
    const int ty = tid >> 4;      // 0..15 -> rows ty*8 .. ty*8+7
    const int tx = tid & 15;      // 0..15 -> cols tx*4 .. tx*4+3
    const int row0 = blockIdx.x * PM;

    float acc[8][4];
#pragma unroll
    for (int i = 0; i < 8; i++)
#pragma unroll
        for (int j = 0; j < 4; j++) acc[i][j] = 0.f;

    for (int k0 = 0; k0 < C_; k0 += PKC) {
        // load x tile: 128x32 floats = 1024 float4 -> 4 per thread
#pragma unroll
        for (int i = 0; i < 4; i++) {
            int idx = tid + i * 256;
            int r = idx >> 3, c = (idx & 7) << 2;
            float4 v = *(const float4*)(x + (size_t)(row0 + r) * C_ + k0 + c);
            *(float4*)&xs[r][c] = v;
        }
        // load W tile: 64x32 floats = 512 float4 -> 2 per thread
#pragma unroll
        for (int i = 0; i < 2; i++) {
            int idx = tid + i * 256;
            int r = idx >> 3, c = (idx & 7) << 2;
            float4 v = *(const float4*)(W + (size_t)r * C_ + k0 + c);
            *(float4*)&ws[r][c] = v;
        }
        __syncthreads();

#pragma unroll
        for (int kk = 0; kk < PKC; kk += 4) {
            float4 a[8], b[4];
#pragma unroll
            for (int i = 0; i < 8; i++) a[i] = *(float4*)&xs[ty * 8 + i][kk];
#pragma unroll
            for (int j = 0; j < 4; j++) b[j] = *(float4*)&ws[tx * 4 + j][kk];
#pragma unroll
            for (int i = 0; i < 8; i++)
#pragma unroll
                for (int j = 0; j < 4; j++)
                    acc[i][j] += a[i].x * b[j].x + a[i].y * b[j].y +
                                 a[i].z * b[j].z + a[i].w * b[j].w;
        }
        __syncthreads();
    }

#pragma unroll
    for (int i = 0; i < 8; i++) {
        float4 v = make_float4(acc[i][0], acc[i][1], acc[i][2], acc[i][3]);
        *(float4*)(out + (size_t)(row0 + ty * 8 + i) * H_ + tx * 4) = v;
    }
}

// ---------------------------------------------------------------------------
// Flash attention (fp32, causal, logits *8).
// BM=128 query rows per block, BN=64 keys per tile, D=64.
// 256 threads; micro-tile 8 rows x 4 cols. Row-state replicated across the
// 16-lane half-warp owning each row group; reductions via shfl_xor (<16).
// ---------------------------------------------------------------------------
#define BM 128
#define BN 64
#define SSTR 68  // smem row stride (floats)

#define ATTN_SMEM ((BM * SSTR + BN * SSTR + BN * SSTR + BM * SSTR) * 4)

__global__ __launch_bounds__(256, 1)
void attn_kernel(float* __restrict__ out)
{
    extern __shared__ float sm[];
    float* qs = sm;                    // BM x SSTR (Q, pre-scaled by 8)
    float* ks = qs + BM * SSTR;        // BN x SSTR
    float* vs = ks + BN * SSTR;        // BN x SSTR
    float* ps = vs + BN * SSTR;        // BM x SSTR (softmax probs)

    const int tid = threadIdx.x;
    const int ty = tid >> 4;           // rows ty*8 .. +7
    const int tx = tid & 15;           // cols/keys tx*4 .. +3
    const int qb = blockIdx.x;
    const int b  = blockIdx.y;
    const int q0 = qb * BM;

    const float* qg = g_q + (size_t)b * T_ * H_;
    const float* kg = g_k + (size_t)b * T_ * H_;
    const float* vg = g_v + (size_t)b * T_ * H_;

    // Load Q tile, folding in the *sqrt(H)=8 logit scale.
#pragma unroll
    for (int i = 0; i < 8; i++) {
        int idx = tid + i * 256;       // 2048 float4 total
        int r = idx >> 4, c = (idx & 15) << 2;
        float4 v = *(const float4*)(qg + (size_t)(q0 + r) * H_ + c);
        v.x *= 8.f; v.y *= 8.f; v.z *= 8.f; v.w *= 8.f;
        *(float4*)&qs[r * SSTR + c] = v;
    }

    float m[8], l[8], o[8][4];
#pragma unroll
    for (int i = 0; i < 8; i++) {
        m[i] = -1e30f; l[i] = 0.f;
#pragma unroll
        for (int j = 0; j < 4; j++) o[i][j] = 0.f;
    }

    const int ntiles = q0 / BN + 2;    // causal: keys up to q0+BM-1

    for (int kb = 0; kb < ntiles; kb++) {
        __syncthreads();               // protect ks/vs/ps reuse
        const int key0 = kb * BN;
        // load K and V tiles: 64x64 each = 1024 float4 each -> 4+4 per thread
#pragma unroll
        for (int i = 0; i < 4; i++) {
            int idx = tid + i * 256;
            int r = idx >> 4, c = (idx & 15) << 2;
            *(float4*)&ks[r * SSTR + c] =
                *(const float4*)(kg + (size_t)(key0 + r) * H_ + c);
            *(float4*)&vs[r * SSTR + c] =
                *(const float4*)(vg + (size_t)(key0 + r) * H_ + c);
        }
        __syncthreads();

        // S = Q_tile @ K_tile^T
        float s[8][4];
#pragma unroll
        for (int i = 0; i < 8; i++)
#pragma unroll
            for (int j = 0; j < 4; j++) s[i][j] = 0.f;

#pragma unroll
        for (int d = 0; d < H_; d += 4) {
            float4 a[8], bb[4];
#pragma unroll
            for (int i = 0; i < 8; i++)
                a[i] = *(float4*)&qs[(ty * 8 + i) * SSTR + d];
#pragma unroll
            for (int j = 0; j < 4; j++)
                bb[j] = *(float4*)&ks[(tx * 4 + j) * SSTR + d];
#pragma unroll
            for (int i = 0; i < 8; i++)
#pragma unroll
                for (int j = 0; j < 4; j++)
                    s[i][j] += a[i].x * bb[j].x + a[i].y * bb[j].y +
                               a[i].z * bb[j].z + a[i].w * bb[j].w;
        }

        // causal mask (only the two diagonal-overlap tiles need it)
        if (key0 + BN > q0) {
#pragma unroll
            for (int i = 0; i < 8; i++)
#pragma unroll
                for (int j = 0; j < 4; j++)
                    if (key0 + tx * 4 + j > q0 + ty * 8 + i) s[i][j] = -1e30f;
        }

        // online softmax update (per row; half-warp reduction over 16 lanes)
#pragma unroll
        for (int i = 0; i < 8; i++) {
            float mx = fmaxf(fmaxf(s[i][0], s[i][1]), fmaxf(s[i][2], s[i][3]));
#pragma unroll
            for (int off = 8; off >= 1; off >>= 1)
                mx = fmaxf(mx, __shfl_xor_sync(0xffffffffu, mx, off));
            float mn = fmaxf(m[i], mx);
            float corr = __expf(m[i] - mn);
            float p0 = __expf(s[i][0] - mn);
            float p1 = __expf(s[i][1] - mn);
            float p2 = __expf(s[i][2] - mn);
            float p3 = __expf(s[i][3] - mn);
            float sum = p0 + p1 + p2 + p3;
#pragma unroll
            for (int off = 8; off >= 1; off >>= 1)
                sum += __shfl_xor_sync(0xffffffffu, sum, off);
            l[i] = l[i] * corr + sum;
            m[i] = mn;
            o[i][0] *= corr; o[i][1] *= corr; o[i][2] *= corr; o[i][3] *= corr;
            *(float4*)&ps[(ty * 8 + i) * SSTR + tx * 4] =
                make_float4(p0, p1, p2, p3);
        }
        __syncthreads();

        // O += P @ V
#pragma unroll
        for (int s0 = 0; s0 < BN; s0 += 4) {
            float4 pa[8], vb[4];
#pragma unroll
            for (int i = 0; i < 8; i++)
                pa[i] = *(float4*)&ps[(ty * 8 + i) * SSTR + s0];
#pragma unroll
            for (int k = 0; k < 4; k++)
                vb[k] = *(float4*)&vs[(s0 + k) * SSTR + tx * 4];
#pragma unroll
            for (int i = 0; i < 8; i++) {
                o[i][0] += pa[i].x * vb[0].x + pa[i].y * vb[1].x +
                           pa[i].z * vb[2].x + pa[i].w * vb[3].x;
                o[i][1] += pa[i].x * vb[0].y + pa[i].y * vb[1].y +
                           pa[i].z * vb[2].y + pa[i].w * vb[3].y;
                o[i][2] += pa[i].x * vb[0].z + pa[i].y * vb[1].z +
                           pa[i].z * vb[2].z + pa[i].w * vb[3].z;
                o[i][3] += pa[i].x * vb[0].w + pa[i].y * vb[1].w +
                           pa[i].z * vb[2].w + pa[i].w * vb[3].w;
            }
        }
    }

    // epilogue: divide by row sums, write [B,T,H]
#pragma unroll
    for (int i = 0; i < 8; i++) {
        float inv = 1.f / l[i];
        float4 v = make_float4(o[i][0] * inv, o[i][1] * inv,
                               o[i][2] * inv, o[i][3] * inv);
        *(float4*)(out + ((size_t)b * T_ + q0 + ty * 8 + i) * H_ + tx * 4) = v;
    }
}

// ---------------------------------------------------------------------------
extern "C" void kernel_launch(void* const* d_in, const int* in_sizes, int n_in,
                              void* d_out, int out_size)
{
    const float* x  = (const float*)d_in[0];
    const float* Wk = (const float*)d_in[1];
    const float* Wq = (const float*)d_in[2];
    const float* Wv = (const float*)d_in[3];
    float* out = (float*)d_out;

    (void)in_sizes; (void)n_in; (void)out_size;

    // idempotent; safe under graph capture (not a stream operation)
    cudaFuncSetAttribute(attn_kernel,
                         cudaFuncAttributeMaxDynamicSharedMemorySize,
                         ATTN_SMEM);

    dim3 pgrid((B_ * T_) / PM, 3);
    proj_kernel<<<pgrid, 256>>>(x, Wk, Wq, Wv);

    dim3 agrid(T_ / BM, B_);
    attn_kernel<<<agrid, 256, ATTN_SMEM>>>(out);
}

// round 10
// speedup vs baseline: 1.2433x; 1.2433x over previous
#include <cuda_runtime.h>
#include <math.h>

#define B_ 8
#define T_ 2048
#define C_ 1024
#define H_ 64

// Scratch for projections (device globals: allocation-free)
__device__ float g_q[B_ * T_ * H_];   // holds 8*q (logit scale folded in)
__device__ float g_k[B_ * T_ * H_];
__device__ float g_v[B_ * T_ * H_];

// ---------------------------------------------------------------------------
// Fused projection GEMM: for W = [Wk; 8*Wq; Wv] (192 rows),
// out[m][h] = sum_c x[m][c] * W[h][c].  M = 16384, N = 192, K = 1024.
// BM=128, BN=192, BK=32; 256 threads; micro-tile 8 rows x (3 x 4) cols.
// Register prefetch of the next k-tile hides global-load latency.
// 128 blocks -> exactly one per SM (one wave, balanced).
// ---------------------------------------------------------------------------
#define PM 128
#define PN 192
#define PKC 32
#define PSTR 36  // smem row stride (floats), float4-aligned

__global__ __launch_bounds__(256, 1)
void proj_kernel(const float* __restrict__ x,
                 const float* __restrict__ Wk,
                 const float* __restrict__ Wq,
                 const float* __restrict__ Wv)
{
    __shared__ float xs[PM][PSTR];   // 18.4 KB
    __shared__ float ws[PN][PSTR];   // 27.6 KB

    const int tid = threadIdx.x;
    const int ty = tid >> 4;      // rows ty*8 .. +7
    const int tx = tid & 15;      // per section: cols tx*4 .. +3
    const int row0 = blockIdx.x * PM;

    // --- precompute load slots ---
    // x tile: 128x32 = 1024 float4 -> 4 per thread
    int xr[4], xc[4];
#pragma unroll
    for (int i = 0; i < 4; i++) {
        int idx = tid + i * 256;
        xr[i] = idx >> 3;
        xc[i] = (idx & 7) << 2;
    }
    // W tile: 192x32 = 1536 float4 -> 6 per thread
    const float* wptr[6];
    float wsc[6];
    int wh[6], wc[6];
#pragma unroll
    for (int i = 0; i < 6; i++) {
        int idx = tid + i * 256;
        int h = idx >> 3;
        wh[i] = h;
        wc[i] = (idx & 7) << 2;
        if (h < 64)       { wptr[i] = Wk + (size_t)h * C_;         wsc[i] = 1.f; }
        else if (h < 128) { wptr[i] = Wq + (size_t)(h - 64) * C_;  wsc[i] = 8.f; }
        else              { wptr[i] = Wv + (size_t)(h - 128) * C_; wsc[i] = 1.f; }
    }

    float acc[8][3][4];
#pragma unroll
    for (int i = 0; i < 8; i++)
#pragma unroll
        for (int s = 0; s < 3; s++)
#pragma unroll
            for (int j = 0; j < 4; j++) acc[i][s][j] = 0.f;

    float4 rx[4], rw[6];
    // prime tile 0
#pragma unroll
    for (int i = 0; i < 4; i++)
        rx[i] = *(const float4*)(x + (size_t)(row0 + xr[i]) * C_ + xc[i]);
#pragma unroll
    for (int i = 0; i < 6; i++) {
        float4 v = *(const float4*)(wptr[i] + wc[i]);
        v.x *= wsc[i]; v.y *= wsc[i]; v.z *= wsc[i]; v.w *= wsc[i];
        rw[i] = v;
    }
#pragma unroll
    for (int i = 0; i < 4; i++) *(float4*)&xs[xr[i]][xc[i]] = rx[i];
#pragma unroll
    for (int i = 0; i < 6; i++) *(float4*)&ws[wh[i]][wc[i]] = rw[i];
    __syncthreads();

    const int NKT = C_ / PKC;  // 32
    for (int kt = 0; kt < NKT; kt++) {
        // prefetch next tile into registers (latency hidden by compute)
        if (kt + 1 < NKT) {
            int kn = (kt + 1) * PKC;
#pragma unroll
            for (int i = 0; i < 4; i++)
                rx[i] = *(const float4*)(x + (size_t)(row0 + xr[i]) * C_ + kn + xc[i]);
#pragma unroll
            for (int i = 0; i < 6; i++) {
                float4 v = *(const float4*)(wptr[i] + kn + wc[i]);
                v.x *= wsc[i]; v.y *= wsc[i]; v.z *= wsc[i]; v.w *= wsc[i];
                rw[i] = v;
            }
        }

        // compute on current smem tile
#pragma unroll
        for (int kk = 0; kk < PKC; kk += 4) {
            float4 a[8];
#pragma unroll
            for (int i = 0; i < 8; i++) a[i] = *(float4*)&xs[ty * 8 + i][kk];
#pragma unroll
            for (int s = 0; s < 3; s++) {
                float4 b[4];
#pragma unroll
                for (int j = 0; j < 4; j++)
                    b[j] = *(float4*)&ws[s * 64 + tx * 4 + j][kk];
#pragma unroll
                for (int i = 0; i < 8; i++)
#pragma unroll
                    for (int j = 0; j < 4; j++)
                        acc[i][s][j] += a[i].x * b[j].x + a[i].y * b[j].y +
                                        a[i].z * b[j].z + a[i].w * b[j].w;
            }
        }
        __syncthreads();
        if (kt + 1 < NKT) {
#pragma unroll
            for (int i = 0; i < 4; i++) *(float4*)&xs[xr[i]][xc[i]] = rx[i];
#pragma unroll
            for (int i = 0; i < 6; i++) *(float4*)&ws[wh[i]][wc[i]] = rw[i];
            __syncthreads();
        }
    }

    // epilogue
#pragma unroll
    for (int s = 0; s < 3; s++) {
        float* out = (s == 0) ? g_k : (s == 1) ? g_q : g_v;
#pragma unroll
        for (int i = 0; i < 8; i++) {
            float4 v = make_float4(acc[i][s][0], acc[i][s][1],
                                   acc[i][s][2], acc[i][s][3]);
            *(float4*)(out + (size_t)(row0 + ty * 8 + i) * H_ + tx * 4) = v;
        }
    }
}

// ---------------------------------------------------------------------------
// Flash attention (fp32, causal; logit scale already folded into g_q).
// BM=64 query rows, BN=64 keys, D=64.  Each block processes TWO q-tiles
// (qb and 31-qb) so every block does exactly 33 equal KV tiles: perfectly
// balanced across the 128 blocks (16 pairs x 8 batches), one wave on 148 SMs.
// 256 threads; micro-tile 4 rows x 4 cols; 16-lane half-warp row reductions.
// ---------------------------------------------------------------------------
#define BM 64
#define BN 64
#define SSTR 68  // smem row stride (floats)

#define ATTN_SMEM (4 * BM * SSTR * 4)   // qs + ks + vs + ps

__global__ __launch_bounds__(256, 1)
void attn_kernel(float* __restrict__ out)
{
    extern __shared__ float sm[];
    float* qs = sm;                    // BM x SSTR
    float* ks = qs + BM * SSTR;        // BN x SSTR
    float* vs = ks + BN * SSTR;        // BN x SSTR
    float* ps = vs + BN * SSTR;        // BM x SSTR

    const int tid = threadIdx.x;
    const int ty = tid >> 4;           // rows ty*4 .. +3
    const int tx = tid & 15;           // cols tx*4 .. +3
    const int b  = blockIdx.y;

    const float* qg = g_q + (size_t)b * T_ * H_;
    const float* kg = g_k + (size_t)b * T_ * H_;
    const float* vg = g_v + (size_t)b * T_ * H_;

    const int NQB = T_ / BM;           // 32

#pragma unroll 1
    for (int pass = 0; pass < 2; pass++) {
        const int qb = pass ? (NQB - 1 - (int)blockIdx.x) : (int)blockIdx.x;
        const int q0 = qb * BM;

        __syncthreads();               // protect smem reuse across passes
        // Load Q tile (already scaled by 8): 64x64 = 1024 float4 -> 4/thread
#pragma unroll
        for (int i = 0; i < 4; i++) {
            int idx = tid + i * 256;
            int r = idx >> 4, c = (idx & 15) << 2;
            *(float4*)&qs[r * SSTR + c] =
                *(const float4*)(qg + (size_t)(q0 + r) * H_ + c);
        }

        float m[4], l[4], o[4][4];
#pragma unroll
        for (int i = 0; i < 4; i++) {
            m[i] = -1e30f; l[i] = 0.f;
#pragma unroll
            for (int j = 0; j < 4; j++) o[i][j] = 0.f;
        }

        const int ntiles = qb + 1;     // causal: KV tiles 0..qb

        for (int kb = 0; kb < ntiles; kb++) {
            __syncthreads();           // ks/vs/ps reuse
            const int key0 = kb * BN;
            // K and V tiles: 64x64 each = 1024 float4 each -> 4+4 per thread
#pragma unroll
            for (int i = 0; i < 4; i++) {
                int idx = tid + i * 256;
                int r = idx >> 4, c = (idx & 15) << 2;
                *(float4*)&ks[r * SSTR + c] =
                    *(const float4*)(kg + (size_t)(key0 + r) * H_ + c);
                *(float4*)&vs[r * SSTR + c] =
                    *(const float4*)(vg + (size_t)(key0 + r) * H_ + c);
            }
            __syncthreads();

            // S = Q_tile @ K_tile^T
            float s[4][4];
#pragma unroll
            for (int i = 0; i < 4; i++)
#pragma unroll
                for (int j = 0; j < 4; j++) s[i][j] = 0.f;

#pragma unroll
            for (int d = 0; d < H_; d += 4) {
                float4 a[4], bb[4];
#pragma unroll
                for (int i = 0; i < 4; i++)
                    a[i] = *(float4*)&qs[(ty * 4 + i) * SSTR + d];
#pragma unroll
                for (int j = 0; j < 4; j++)
                    bb[j] = *(float4*)&ks[(tx * 4 + j) * SSTR + d];
#pragma unroll
                for (int i = 0; i < 4; i++)
#pragma unroll
                    for (int j = 0; j < 4; j++)
                        s[i][j] += a[i].x * bb[j].x + a[i].y * bb[j].y +
                                   a[i].z * bb[j].z + a[i].w * bb[j].w;
            }

            // causal mask: only the diagonal tile needs it
            if (kb == qb) {
#pragma unroll
                for (int i = 0; i < 4; i++)
#pragma unroll
                    for (int j = 0; j < 4; j++)
                        if (key0 + tx * 4 + j > q0 + ty * 4 + i)
                            s[i][j] = -1e30f;
            }

            // online softmax (per row; 16-lane half-warp reductions)
#pragma unroll
            for (int i = 0; i < 4; i++) {
                float mx = fmaxf(fmaxf(s[i][0], s[i][1]),
                                 fmaxf(s[i][2], s[i][3]));
#pragma unroll
                for (int off = 8; off >= 1; off >>= 1)
                    mx = fmaxf(mx, __shfl_xor_sync(0xffffffffu, mx, off));
                float mn = fmaxf(m[i], mx);
                float corr = __expf(m[i] - mn);
                float p0 = __expf(s[i][0] - mn);
                float p1 = __expf(s[i][1] - mn);
                float p2 = __expf(s[i][2] - mn);
                float p3 = __expf(s[i][3] - mn);
                float sum = p0 + p1 + p2 + p3;
#pragma unroll
                for (int off = 8; off >= 1; off >>= 1)
                    sum += __shfl_xor_sync(0xffffffffu, sum, off);
                l[i] = l[i] * corr + sum;
                m[i] = mn;
                o[i][0] *= corr; o[i][1] *= corr;
                o[i][2] *= corr; o[i][3] *= corr;
                *(float4*)&ps[(ty * 4 + i) * SSTR + tx * 4] =
                    make_float4(p0, p1, p2, p3);
            }
            __syncthreads();

            // O += P @ V
#pragma unroll
            for (int s0 = 0; s0 < BN; s0 += 4) {
                float4 pa[4], vb[4];
#pragma unroll
                for (int i = 0; i < 4; i++)
                    pa[i] = *(float4*)&ps[(ty * 4 + i) * SSTR + s0];
#pragma unroll
                for (int k = 0; k < 4; k++)
                    vb[k] = *(float4*)&vs[(s0 + k) * SSTR + tx * 4];
#pragma unroll
                for (int i = 0; i < 4; i++) {
                    o[i][0] += pa[i].x * vb[0].x + pa[i].y * vb[1].x +
                               pa[i].z * vb[2].x + pa[i].w * vb[3].x;
                    o[i][1] += pa[i].x * vb[0].y + pa[i].y * vb[1].y +
                               pa[i].z * vb[2].y + pa[i].w * vb[3].y;
                    o[i][2] += pa[i].x * vb[0].z + pa[i].y * vb[1].z +
                               pa[i].z * vb[2].z + pa[i].w * vb[3].z;
                    o[i][3] += pa[i].x * vb[0].w + pa[i].y * vb[1].w +
                               pa[i].z * vb[2].w + pa[i].w * vb[3].w;
                }
            }
        }

        // epilogue: divide by row sums, write [B,T,H]
#pragma unroll
        for (int i = 0; i < 4; i++) {
            float inv = 1.f / l[i];
            float4 v = make_float4(o[i][0] * inv, o[i][1] * inv,
                                   o[i][2] * inv, o[i][3] * inv);
            *(float4*)(out + ((size_t)b * T_ + q0 + ty * 4 + i) * H_ + tx * 4) = v;
        }
    }
}

// ---------------------------------------------------------------------------
extern "C" void kernel_launch(void* const* d_in, const int* in_sizes, int n_in,
                              void* d_out, int out_size)
{
    const float* x  = (const float*)d_in[0];
    const float* Wk = (const float*)d_in[1];
    const float* Wq = (const float*)d_in[2];
    const float* Wv = (const float*)d_in[3];
    float* out = (float*)d_out;

    (void)in_sizes; (void)n_in; (void)out_size;

    cudaFuncSetAttribute(attn_kernel,
                         cudaFuncAttributeMaxDynamicSharedMemorySize,
                         ATTN_SMEM);

    dim3 pgrid((B_ * T_) / PM, 1);
    proj_kernel<<<pgrid, 256>>>(x, Wk, Wq, Wv);

    dim3 agrid((T_ / BM) / 2, B_);   // 16 balanced pairs x 8 batches
    attn_kernel<<<agrid, 256, ATTN_SMEM>>>(out);
}